// round 4
// baseline (speedup 1.0000x reference)
#include <cuda_runtime.h>
#include <cuda_bf16.h>

typedef unsigned long long ull;

#define IMG 224
#define B 16
#define NC 128
#define HW1 (IMG*IMG)
#define HW2 (112*112)
#define XDP 38400

// ---------------- static device scratch ----------------
__device__ float  g_out224[(size_t)B*NC*HW1];  // (16,128,224,224)
__device__ float  g_x112 [(size_t)B*NC*HW2];   // after bn1+relu+maxpool
__device__ float  g_y112 [(size_t)B*NC*HW2];   // conv2 raw output
__device__ float  g_xd   [(size_t)B*3*XDP];    // downsampled windows
__device__ double g_red  [2][2][NC];           // [layer][sum|sumsq][c]
__device__ float2 g_ss   [2][NC];              // [layer][c] = (scale, shift)

// window table passed by value: 28 windows x 9 fields: t,l,h,w,sh,sw,xoff,ds0,b10
struct WinTab { int f[28*9]; };

// ---------------- f32x2 helpers ----------------
__device__ __forceinline__ ull ffma2(ull a, ull b, ull c){
    ull d; asm("fma.rn.f32x2 %0, %1, %2, %3;" : "=l"(d) : "l"(a), "l"(b), "l"(c));
    return d;
}
__device__ __forceinline__ ull pack2(float x){
    ull d; asm("mov.b64 %0, {%1, %1};" : "=l"(d) : "f"(x));
    return d;
}
__device__ __forceinline__ float2 unpack2(ull v){
    float2 r; asm("mov.b64 {%0, %1}, %2;" : "=f"(r.x), "=f"(r.y) : "l"(v));
    return r;
}

// ---------------- downsample (jax.image.resize linear+antialias) ----------------
// grid.x = sum over windows of sh*ceil(sw/64); grid.z = B*3; 64 threads
__global__ void ds_all(const float* __restrict__ inp, WinTab wt){
    int bx = blockIdx.x;
    int wi = 0;
    while (wi < 27 && bx >= wt.f[(wi+1)*9+7]) wi++;
    const int* W = &wt.f[wi*9];
    int t=W[0], l=W[1], h=W[2], w=W[3], sh=W[4], sw=W[5], xoff=W[6];
    int loc = bx - W[7];
    int cb = (sw + 63) >> 6;
    int oy = loc / cb;
    int ox = (loc - oy*cb)*64 + threadIdx.x;
    if (ox >= sw) return;
    int inH = h + 12, inW = w + 12;

    // y weights (jax: f32 triangle kernel, normalize over in-range taps)
    float invy = (float)((double)inH/(double)sh);
    float ksy  = fmaxf(invy, 1.0f);
    float sfy  = ((float)oy + 0.5f)*invy - 0.5f;
    int y0 = (int)ceilf(sfy - ksy); if (y0 < 0) y0 = 0;
    int y1 = (int)floorf(sfy + ksy); if (y1 > inH-1) y1 = inH-1;
    int ny = y1 - y0 + 1; if (ny > 6) ny = 6;
    float wy[6], ty = 0.f;
    for (int i = 0; i < ny; i++){
        float v = 1.0f - fabsf(sfy - (float)(y0+i))/ksy;
        wy[i] = v > 0.f ? v : 0.f; ty += wy[i];
    }
    // x weights
    float invx = (float)((double)inW/(double)sw);
    float ksx  = fmaxf(invx, 1.0f);
    float sfx  = ((float)ox + 0.5f)*invx - 0.5f;
    int x0 = (int)ceilf(sfx - ksx); if (x0 < 0) x0 = 0;
    int x1 = (int)floorf(sfx + ksx); if (x1 > inW-1) x1 = inW-1;
    int nx = x1 - x0 + 1; if (nx > 6) nx = 6;
    float wx[6], tx = 0.f;
    for (int i = 0; i < nx; i++){
        float v = 1.0f - fabsf(sfx - (float)(x0+i))/ksx;
        wx[i] = v > 0.f ? v : 0.f; tx += wx[i];
    }

    const float* base = inp + (size_t)blockIdx.z * HW1;
    float acc = 0.f;
    for (int iy = 0; iy < ny; iy++){
        int gy = t + y0 + iy - 6;            // padded-window row -> image row
        if ((unsigned)gy >= (unsigned)IMG) continue;
        const float* row = base + gy*IMG;
        float ra = 0.f;
        for (int ix = 0; ix < nx; ix++){
            int gx = l + x0 + ix - 6;
            float v = ((unsigned)gx < (unsigned)IMG) ? row[gx] : 0.f;
            ra += wx[ix]*v;
        }
        acc += wy[iy]*ra;
    }
    g_xd[(size_t)blockIdx.z*XDP + xoff + oy*sw + ox] = acc / (ty*tx);
}

// ---------------- conv1 7x7 VALID (3->128) + nearest-up scatter ----------------
// grid.x = sum of ceil(hin/8)*ceil(win/8); grid.z = B*2 (oc halves); 256 threads
__global__ __launch_bounds__(256,2) void conv1_all(const float* __restrict__ w1, WinTab wt){
    __shared__ __align__(16) float ws[147*64];   // [k][oc]  k = c*49+ky*7+kx
    __shared__ __align__(16) ull   ins[3*14*14]; // [c][14][14], dup'd f32x2
    int bx = blockIdx.x;
    int wi = 0;
    while (wi < 27 && bx >= wt.f[(wi+1)*9+8]) wi++;
    const int* W = &wt.f[wi*9];
    int t=W[0], l=W[1], h=W[2], w=W[3], sh=W[4], sw=W[5], xoff=W[6];
    int loc = bx - W[8];
    int hin = sh - 6, win = sw - 6;
    int bwx = (win + 7) >> 3;
    int ty8 = loc / bwx, tx8 = loc - ty8*bwx;
    int fy0 = ty8*8, fx0 = tx8*8;
    int b = blockIdx.z >> 1, ocbase = (blockIdx.z & 1)*64;
    int tid = threadIdx.x;

    { // stage weights (each quad of threads covers one oc row of 147)
        int o = tid >> 2, k0 = (tid & 3)*37;
        const float* wr = w1 + (size_t)(ocbase + o)*147;
        #pragma unroll
        for (int j = 0; j < 37; j++){
            int k = k0 + j;
            if (k < 147) ws[k*64 + o] = wr[k];
        }
    }
    for (int i = tid; i < 588; i += 256){
        int c = i/196, rem = i - c*196, ry = rem/14, rx = rem - ry*14;
        int gy = fy0 + ry, gx = fx0 + rx;
        float v = 0.f;
        if (gy < sh && gx < sw)
            v = g_xd[(size_t)(b*3 + c)*XDP + xoff + gy*sw + gx];
        ins[i] = pack2(v);
    }
    __syncthreads();

    int ocg = tid & 15;       // 4 oc = ocg*4
    int pxg = tid >> 4;       // 4 px: p = pxg*4 + j
    int p0  = pxg*4;
    int py  = p0 >> 3, px0 = p0 & 7;   // px0 in {0,4} (even)

    ull acc[2][4] = {{0,0,0,0},{0,0,0,0}};
    for (int c = 0; c < 3; c++){
      #pragma unroll
      for (int ky = 0; ky < 7; ky++){
        const ull* iprow = &ins[c*196 + (py+ky)*14 + px0];
        #pragma unroll
        for (int kx = 0; kx < 7; kx++){
            ulonglong2 wv = *(const ulonglong2*)&ws[(c*49 + ky*7 + kx)*64 + ocg*4];
            if ((kx & 1) == 0){     // 16B-aligned: vector loads
                ulonglong2 a01 = *(const ulonglong2*)(iprow + kx);
                ulonglong2 a23 = *(const ulonglong2*)(iprow + kx + 2);
                acc[0][0] = ffma2(wv.x, a01.x, acc[0][0]);
                acc[1][0] = ffma2(wv.y, a01.x, acc[1][0]);
                acc[0][1] = ffma2(wv.x, a01.y, acc[0][1]);
                acc[1][1] = ffma2(wv.y, a01.y, acc[1][1]);
                acc[0][2] = ffma2(wv.x, a23.x, acc[0][2]);
                acc[1][2] = ffma2(wv.y, a23.x, acc[1][2]);
                acc[0][3] = ffma2(wv.x, a23.y, acc[0][3]);
                acc[1][3] = ffma2(wv.y, a23.y, acc[1][3]);
            } else {
                #pragma unroll
                for (int j = 0; j < 4; j++){
                    ull iv2 = iprow[kx + j];
                    acc[0][j] = ffma2(wv.x, iv2, acc[0][j]);
                    acc[1][j] = ffma2(wv.y, iv2, acc[1][j]);
                }
            }
        }
      }
    }

    // nearest-up scatter: out y with y*hin//h == fy  (empty range when hin>h)
    #pragma unroll
    for (int j = 0; j < 4; j++){
        int fy = fy0 + py, fx = fx0 + px0 + j;
        if (fy >= hin || fx >= win) continue;
        int ys = (fy*h + hin - 1)/hin;
        int ye = ((fy+1)*h + hin - 1)/hin - 1;
        int xs = (fx*w + win - 1)/win;
        int xe = ((fx+1)*w + win - 1)/win - 1;
        if (ys > ye || xs > xe) continue;
        float2 v0 = unpack2(acc[0][j]), v1 = unpack2(acc[1][j]);
        float vals[4] = {v0.x, v0.y, v1.x, v1.y};
        #pragma unroll
        for (int oi = 0; oi < 4; oi++){
            float* op = g_out224 + ((size_t)(b*NC + ocbase + ocg*4 + oi)*IMG + t)*IMG + l;
            for (int y = ys; y <= ye; y++)
                for (int x = xs; x <= xe; x++)
                    op[y*IMG + x] = vals[oi];
        }
    }
}

// ---------------- BN batch stats ----------------
__global__ void zero_red(){
    if (threadIdx.x < 512) ((double*)g_red)[threadIdx.x] = 0.0;
}

__global__ void bn_accum(int sel, int HW, int layer){
    const float* src = sel ? g_y112 : g_out224;
    int c = blockIdx.y;
    int per = (HW + gridDim.x - 1)/gridDim.x;
    int s0 = blockIdx.x*per;
    int s1 = s0 + per; if (s1 > HW) s1 = HW;
    float s = 0.f, sq = 0.f;
    for (int b = 0; b < B; b++){
        const float* p = src + ((size_t)b*NC + c)*HW;
        for (int i = s0 + threadIdx.x; i < s1; i += blockDim.x){
            float v = p[i]; s += v; sq += v*v;
        }
    }
    for (int o = 16; o; o >>= 1){
        s  += __shfl_down_sync(0xffffffffu, s,  o);
        sq += __shfl_down_sync(0xffffffffu, sq, o);
    }
    if ((threadIdx.x & 31) == 0){
        atomicAdd(&g_red[layer][0][c], (double)s);
        atomicAdd(&g_red[layer][1][c], (double)sq);
    }
}

__global__ void bn_finalize(const float* __restrict__ g, const float* __restrict__ bta,
                            int layer, double invN){
    int c = threadIdx.x;
    if (c >= NC) return;
    double m   = g_red[layer][0][c]*invN;
    double var = g_red[layer][1][c]*invN - m*m;
    float rs = (float)(1.0/sqrt(var + 1e-5));
    float sc = g[c]*rs;
    g_ss[layer][c] = make_float2(sc, bta[c] - (float)m*sc);
}

// ---------------- bn1 + relu + maxpool 3x3 s2 p1 ----------------
__global__ void pool_bn1(){
    int idx = blockIdx.x*256 + threadIdx.x;
    if (idx >= B*NC*HW2) return;
    int ox = idx % 112;
    int t1 = idx / 112;
    int oy = t1 % 112;
    int t2 = t1 / 112;
    int c  = t2 % NC;
    int bb = t2 / NC;
    float2 ss = g_ss[0][c];
    const float* p = g_out224 + (size_t)(bb*NC + c)*HW1;
    float m = 0.f; // all in-range candidates are relu'd (>=0); -inf pad excluded
    #pragma unroll
    for (int i = 0; i < 3; i++){
        int y = 2*oy - 1 + i;
        if ((unsigned)y >= (unsigned)IMG) continue;
        #pragma unroll
        for (int j = 0; j < 3; j++){
            int x = 2*ox - 1 + j;
            if ((unsigned)x >= (unsigned)IMG) continue;
            float v = fmaxf(p[y*IMG + x]*ss.x + ss.y, 0.f);
            m = fmaxf(m, v);
        }
    }
    g_x112[idx] = m;
}

// ---------------- conv2 3x3 pad1 (128->128) on 112x112 ----------------
// grid (7,7,B*2); 256 threads; 64 oc x 16x16 px per block; ic in chunks of 8
__global__ __launch_bounds__(256,2) void conv2_all(const float* __restrict__ w2){
    __shared__ __align__(16) float ws[72*64];      // [icl*9+tap][oc]
    __shared__ __align__(16) ull   ins[8*18*20];   // [icl][18 rows][20 stride], dup'd
    int oy0 = blockIdx.y*16, ox0 = blockIdx.x*16;
    int b = blockIdx.z >> 1, ocbase = (blockIdx.z & 1)*64;
    int tid = threadIdx.x;
    int ocg = tid & 15, pxg = tid >> 4;
    int r0 = (pxg >> 2)*4, c0 = (pxg & 3)*4;   // c0 even

    ull acc[2][16];
    #pragma unroll
    for (int i = 0; i < 16; i++){ acc[0][i] = 0; acc[1][i] = 0; }

    for (int icc = 0; icc < 16; icc++){
        __syncthreads();
        { // stage 8ic x 9tap x 64oc weights (quad of threads covers 72 floats/oc)
            int o = tid >> 2, k0 = (tid & 3)*18;
            const float* wr = w2 + ((size_t)(ocbase + o)*NC + icc*8)*9;
            #pragma unroll
            for (int j = 0; j < 18; j++)
                ws[(k0 + j)*64 + o] = wr[k0 + j];
        }
        for (int i = tid; i < 8*18*18; i += 256){
            int icl = i/324, rem = i - icl*324, y = rem/18, x = rem - y*18;
            int gy = oy0 - 1 + y, gx = ox0 - 1 + x;
            float v = 0.f;
            if ((unsigned)gy < 112u && (unsigned)gx < 112u)
                v = g_x112[((size_t)(b*NC + icc*8 + icl)*112 + gy)*112 + gx];
            ins[(icl*18 + y)*20 + x] = pack2(v);
        }
        __syncthreads();

        for (int icl = 0; icl < 8; icl++){
            #pragma unroll
            for (int ky = 0; ky < 3; ky++){
                const ull* iprow = &ins[(icl*18 + r0 + ky)*20 + c0];
                #pragma unroll
                for (int kx = 0; kx < 3; kx++){
                    ulonglong2 wv = *(const ulonglong2*)&ws[((icl*9 + ky*3 + kx)<<6) + ocg*4];
                    if (kx != 1){   // 16B-aligned: vector loads
                        #pragma unroll
                        for (int pyy = 0; pyy < 4; pyy++){
                            ulonglong2 a01 = *(const ulonglong2*)(iprow + pyy*20 + kx);
                            ulonglong2 a23 = *(const ulonglong2*)(iprow + pyy*20 + kx + 2);
                            acc[0][pyy*4+0] = ffma2(wv.x, a01.x, acc[0][pyy*4+0]);
                            acc[1][pyy*4+0] = ffma2(wv.y, a01.x, acc[1][pyy*4+0]);
                            acc[0][pyy*4+1] = ffma2(wv.x, a01.y, acc[0][pyy*4+1]);
                            acc[1][pyy*4+1] = ffma2(wv.y, a01.y, acc[1][pyy*4+1]);
                            acc[0][pyy*4+2] = ffma2(wv.x, a23.x, acc[0][pyy*4+2]);
                            acc[1][pyy*4+2] = ffma2(wv.y, a23.x, acc[1][pyy*4+2]);
                            acc[0][pyy*4+3] = ffma2(wv.x, a23.y, acc[0][pyy*4+3]);
                            acc[1][pyy*4+3] = ffma2(wv.y, a23.y, acc[1][pyy*4+3]);
                        }
                    } else {
                        #pragma unroll
                        for (int pyy = 0; pyy < 4; pyy++){
                            #pragma unroll
                            for (int pxx = 0; pxx < 4; pxx++){
                                ull iv2 = iprow[pyy*20 + kx + pxx];
                                acc[0][pyy*4+pxx] = ffma2(wv.x, iv2, acc[0][pyy*4+pxx]);
                                acc[1][pyy*4+pxx] = ffma2(wv.y, iv2, acc[1][pyy*4+pxx]);
                            }
                        }
                    }
                }
            }
        }
    }

    #pragma unroll
    for (int pyy = 0; pyy < 4; pyy++){
        #pragma unroll
        for (int pxx = 0; pxx < 4; pxx++){
            int gy = oy0 + r0 + pyy, gx = ox0 + c0 + pxx;
            float2 v0 = unpack2(acc[0][pyy*4+pxx]);
            float2 v1 = unpack2(acc[1][pyy*4+pxx]);
            size_t base = ((size_t)(b*NC + ocbase + ocg*4)*112 + gy)*112 + gx;
            g_y112[base]            = v0.x;
            g_y112[base +   HW2]    = v0.y;
            g_y112[base + 2*HW2]    = v1.x;
            g_y112[base + 3*HW2]    = v1.y;
        }
    }
}

// ---------------- final bn2 + relu ----------------
__global__ void finalize_out(float* __restrict__ out){
    int idx = blockIdx.x*256 + threadIdx.x;
    if (idx >= B*NC*HW2) return;
    int c = (idx / HW2) % NC;
    float2 ss = g_ss[1][c];
    out[idx] = fmaxf(g_y112[idx]*ss.x + ss.y, 0.f);
}

// ---------------- host: window geometry (replicates numpy/float32 exactly) ------
static void build_wins(int* Wt, int* dstot, int* b1tot){
    float scales[7];
    for (int i = 0; i < 7; i++){
        double v = 2.0 + (double)i*((1.0 - 2.0)/6.0);
        if (i == 6) v = 1.0;
        scales[i] = (float)v;
    }
    int xoff = 0, ds = 0, b1 = 0, wi = 0;
    for (int s = 0; s < 7; s++){
        int a = 16*s, bb = 16*(s+1), c = 224 - bb, d = 224 - a;
        int rect[4][4] = {{a,a,bb,c},{bb,a,d,bb},{c,bb,d,d},{a,c,c,d}};
        for (int r = 0; r < 4; r++){
            int t = rect[r][0], l = rect[r][1], bo = rect[r][2], rr = rect[r][3];
            int h = bo - t, w = rr - l;
            volatile float fh = (float)(h + 12), fw = (float)(w + 12);
            int sh = (int)(fh / scales[s]);
            int sw = (int)(fw / scales[s]);
            int* e = Wt + wi*9;
            e[0]=t; e[1]=l; e[2]=h; e[3]=w; e[4]=sh; e[5]=sw;
            e[6]=xoff; e[7]=ds; e[8]=b1;
            xoff += sh*sw;
            ds   += sh * ((sw + 63)/64);
            int hin = sh - 6, win = sw - 6;
            b1   += ((hin + 7)/8) * ((win + 7)/8);
            wi++;
        }
    }
    *dstot = ds; *b1tot = b1;
}

extern "C" void kernel_launch(void* const* d_in, const int* in_sizes, int n_in,
                              void* d_out, int out_size){
    const float* inp    = (const float*)d_in[0];
    const float* w1     = (const float*)d_in[1];
    const float* gamma1 = (const float*)d_in[2];
    const float* beta1  = (const float*)d_in[3];
    const float* w2     = (const float*)d_in[4];
    const float* gamma2 = (const float*)d_in[5];
    const float* beta2  = (const float*)d_in[6];
    float* out = (float*)d_out;

    WinTab wt;
    int dstot = 0, b1tot = 0;
    build_wins(wt.f, &dstot, &b1tot);

    ds_all<<<dim3(dstot,1,B*3), 64>>>(inp, wt);
    conv1_all<<<dim3(b1tot,1,B*2), 256>>>(w1, wt);
    zero_red<<<1,512>>>();
    bn_accum<<<dim3(64,NC), 256>>>(0, HW1, 0);
    bn_finalize<<<1,128>>>(gamma1, beta1, 0, 1.0/((double)B*HW1));
    pool_bn1<<<(B*NC*HW2 + 255)/256, 256>>>();
    conv2_all<<<dim3(7,7,B*2), 256>>>(w2);
    bn_accum<<<dim3(16,NC), 256>>>(1, HW2, 1);
    bn_finalize<<<1,128>>>(gamma2, beta2, 1, 1.0/((double)B*HW2));
    finalize_out<<<(B*NC*HW2 + 255)/256, 256>>>(out);
}

// round 10
// speedup vs baseline: 1.0190x; 1.0190x over previous
#include <cuda_runtime.h>
#include <cuda_bf16.h>

typedef unsigned long long ull;

#define IMG 224
#define B 16
#define NC 128
#define HW1 (IMG*IMG)
#define HW2 (112*112)
#define XDP 38400

// ---------------- static device scratch ----------------
__device__ float  g_out224[(size_t)B*NC*HW1];  // (16,128,224,224)
__device__ float  g_x112 [(size_t)B*NC*HW2];   // after bn1+relu+maxpool
__device__ float  g_y112 [(size_t)B*NC*HW2];   // conv2 raw output
__device__ float  g_xd   [(size_t)B*3*XDP];    // downsampled windows
__device__ double g_red  [2][2][NC];           // [layer][sum|sumsq][c]
__device__ float2 g_ss   [2][NC];              // [layer][c] = (scale, shift)

// window table passed by value: 28 windows x 9 fields: t,l,h,w,sh,sw,xoff,ds0,b10
struct WinTab { int f[28*9]; };

// ---------------- f32x2 helpers ----------------
__device__ __forceinline__ ull ffma2(ull a, ull b, ull c){
    ull d; asm("fma.rn.f32x2 %0, %1, %2, %3;" : "=l"(d) : "l"(a), "l"(b), "l"(c));
    return d;
}
__device__ __forceinline__ ull pack2(float x){
    ull d; asm("mov.b64 %0, {%1, %1};" : "=l"(d) : "f"(x));
    return d;
}
__device__ __forceinline__ float2 unpack2(ull v){
    float2 r; asm("mov.b64 {%0, %1}, %2;" : "=f"(r.x), "=f"(r.y) : "l"(v));
    return r;
}

// ---------------- downsample (jax.image.resize linear+antialias) ----------------
__global__ void ds_all(const float* __restrict__ inp, WinTab wt){
    int bx = blockIdx.x;
    int wi = 0;
    while (wi < 27 && bx >= wt.f[(wi+1)*9+7]) wi++;
    const int* W = &wt.f[wi*9];
    int t=W[0], l=W[1], h=W[2], w=W[3], sh=W[4], sw=W[5], xoff=W[6];
    int loc = bx - W[7];
    int cb = (sw + 63) >> 6;
    int oy = loc / cb;
    int ox = (loc - oy*cb)*64 + threadIdx.x;
    if (ox >= sw) return;
    int inH = h + 12, inW = w + 12;

    float invy = (float)((double)inH/(double)sh);
    float ksy  = fmaxf(invy, 1.0f);
    float sfy  = ((float)oy + 0.5f)*invy - 0.5f;
    int y0 = (int)ceilf(sfy - ksy); if (y0 < 0) y0 = 0;
    int y1 = (int)floorf(sfy + ksy); if (y1 > inH-1) y1 = inH-1;
    int ny = y1 - y0 + 1; if (ny > 6) ny = 6;
    float wy[6], ty = 0.f;
    for (int i = 0; i < ny; i++){
        float v = 1.0f - fabsf(sfy - (float)(y0+i))/ksy;
        wy[i] = v > 0.f ? v : 0.f; ty += wy[i];
    }
    float invx = (float)((double)inW/(double)sw);
    float ksx  = fmaxf(invx, 1.0f);
    float sfx  = ((float)ox + 0.5f)*invx - 0.5f;
    int x0 = (int)ceilf(sfx - ksx); if (x0 < 0) x0 = 0;
    int x1 = (int)floorf(sfx + ksx); if (x1 > inW-1) x1 = inW-1;
    int nx = x1 - x0 + 1; if (nx > 6) nx = 6;
    float wx[6], tx = 0.f;
    for (int i = 0; i < nx; i++){
        float v = 1.0f - fabsf(sfx - (float)(x0+i))/ksx;
        wx[i] = v > 0.f ? v : 0.f; tx += wx[i];
    }

    const float* base = inp + (size_t)blockIdx.z * HW1;
    float acc = 0.f;
    for (int iy = 0; iy < ny; iy++){
        int gy = t + y0 + iy - 6;
        if ((unsigned)gy >= (unsigned)IMG) continue;
        const float* row = base + gy*IMG;
        float ra = 0.f;
        for (int ix = 0; ix < nx; ix++){
            int gx = l + x0 + ix - 6;
            float v = ((unsigned)gx < (unsigned)IMG) ? row[gx] : 0.f;
            ra += wx[ix]*v;
        }
        acc += wy[iy]*ra;
    }
    g_xd[(size_t)blockIdx.z*XDP + xoff + oy*sw + ox] = acc / (ty*tx);
}

// ---------------- conv1 7x7 VALID (3->128) + coalesced nearest-up + fused stats --
// grid.x = sum of ceil(hin/8)*ceil(win/8); grid.z = B*2 (oc halves); 256 threads
// smem phase A: ws[147*64] (37632B) + ins[588] ull (4704B) = 42336B
// smem phase B (overlay on ws): sval[64*65] f (16640B) + iymap[24] + ixmap[24]
__global__ __launch_bounds__(256,2) void conv1_all(const float* __restrict__ w1, WinTab wt){
    __shared__ __align__(16) char smem1[42336];
    __shared__ float ssum[64], ssq[64];
    float* ws  = (float*)smem1;                 // [k][oc]
    ull*   ins = (ull*)(smem1 + 37632);         // [c][14][14] dup'd f32x2
    float* sval  = (float*)smem1;               // [oc][65] store-phase
    int*   iymap = (int*)(smem1 + 16640);
    int*   ixmap = (int*)(smem1 + 16640 + 96);

    int bx = blockIdx.x;
    int wi = 0;
    while (wi < 27 && bx >= wt.f[(wi+1)*9+8]) wi++;
    const int* W = &wt.f[wi*9];
    int t=W[0], l=W[1], h=W[2], w=W[3], sh=W[4], sw=W[5], xoff=W[6];
    int loc = bx - W[8];
    int hin = sh - 6, win = sw - 6;
    int bwx = (win + 7) >> 3;
    int ty8 = loc / bwx, tx8 = loc - ty8*bwx;
    int fy0 = ty8*8, fx0 = tx8*8;
    int b = blockIdx.z >> 1, ocbase = (blockIdx.z & 1)*64;
    int tid = threadIdx.x;

    if (tid < 64){ ssum[tid] = 0.f; ssq[tid] = 0.f; }

    { // stage weights
        int o = tid >> 2, k0 = (tid & 3)*37;
        const float* wr = w1 + (size_t)(ocbase + o)*147;
        #pragma unroll
        for (int j = 0; j < 37; j++){
            int k = k0 + j;
            if (k < 147) ws[k*64 + o] = wr[k];
        }
    }
    for (int i = tid; i < 588; i += 256){
        int c = i/196, rem = i - c*196, ry = rem/14, rx = rem - ry*14;
        int gy = fy0 + ry, gx = fx0 + rx;
        float v = 0.f;
        if (gy < sh && gx < sw)
            v = g_xd[(size_t)(b*3 + c)*XDP + xoff + gy*sw + gx];
        ins[i] = pack2(v);
    }
    __syncthreads();

    int ocg = tid & 15;       // 4 oc = ocg*4..+3
    int pxg = tid >> 4;       // 4 px: p = pxg*4 + j
    int p0  = pxg*4;
    int py  = p0 >> 3, px0 = p0 & 7;   // px0 in {0,4}

    ull acc[2][4] = {{0,0,0,0},{0,0,0,0}};
    for (int c = 0; c < 3; c++){
      #pragma unroll
      for (int ky = 0; ky < 7; ky++){
        const ull* iprow = &ins[c*196 + (py+ky)*14 + px0];
        #pragma unroll
        for (int kx = 0; kx < 7; kx++){
            ulonglong2 wv = *(const ulonglong2*)&ws[(c*49 + ky*7 + kx)*64 + ocg*4];
            if ((kx & 1) == 0){
                ulonglong2 a01 = *(const ulonglong2*)(iprow + kx);
                ulonglong2 a23 = *(const ulonglong2*)(iprow + kx + 2);
                acc[0][0] = ffma2(wv.x, a01.x, acc[0][0]);
                acc[1][0] = ffma2(wv.y, a01.x, acc[1][0]);
                acc[0][1] = ffma2(wv.x, a01.y, acc[0][1]);
                acc[1][1] = ffma2(wv.y, a01.y, acc[1][1]);
                acc[0][2] = ffma2(wv.x, a23.x, acc[0][2]);
                acc[1][2] = ffma2(wv.y, a23.x, acc[1][2]);
                acc[0][3] = ffma2(wv.x, a23.y, acc[0][3]);
                acc[1][3] = ffma2(wv.y, a23.y, acc[1][3]);
            } else {
                #pragma unroll
                for (int j = 0; j < 4; j++){
                    ull iv2 = iprow[kx + j];
                    acc[0][j] = ffma2(wv.x, iv2, acc[0][j]);
                    acc[1][j] = ffma2(wv.y, iv2, acc[1][j]);
                }
            }
        }
      }
    }

    // unpack values; fused BN1 stats weighted by nearest-up replication count
    float vals[4][4]; // [oi][j]
    #pragma unroll
    for (int j = 0; j < 4; j++){
        float2 v0 = unpack2(acc[0][j]), v1 = unpack2(acc[1][j]);
        vals[0][j] = v0.x; vals[1][j] = v0.y; vals[2][j] = v1.x; vals[3][j] = v1.y;
    }
    {
        float cnt[4];
        int fy = fy0 + py;
        int ysr = (fy*h + hin - 1)/hin;
        int yer = ((fy+1)*h + hin - 1)/hin - 1;
        int ch = (fy < hin) ? (yer - ysr + 1) : 0;
        #pragma unroll
        for (int j = 0; j < 4; j++){
            int fx = fx0 + px0 + j;
            int xsr = (fx*w + win - 1)/win;
            int xer = ((fx+1)*w + win - 1)/win - 1;
            int cw = (fx < win) ? (xer - xsr + 1) : 0;
            cnt[j] = (float)(ch*cw);
        }
        #pragma unroll
        for (int oi = 0; oi < 4; oi++){
            float s = 0.f, q = 0.f;
            #pragma unroll
            for (int j = 0; j < 4; j++){
                float v = vals[oi][j];
                s += v*cnt[j]; q += v*v*cnt[j];
            }
            atomicAdd(&ssum[ocg*4+oi], s);
            atomicAdd(&ssq [ocg*4+oi], q);
        }
    }

    __syncthreads();   // ws/ins dead -> overlay sval
    #pragma unroll
    for (int oi = 0; oi < 4; oi++)
        #pragma unroll
        for (int j = 0; j < 4; j++)
            sval[(ocg*4+oi)*65 + p0 + j] = vals[oi][j];

    // out-footprint of this tile + nearest-up index maps
    int fy_hi = min(fy0 + 8, hin), fx_hi = min(fx0 + 8, win);
    int ys_blk = (fy0*h + hin - 1)/hin;
    int ye_blk = (fy_hi*h + hin - 1)/hin - 1;
    int xs_blk = (fx0*w + win - 1)/win;
    int xe_blk = (fx_hi*w + win - 1)/win - 1;
    int R = ye_blk - ys_blk + 1, C = xe_blk - xs_blk + 1;   // each <= 17
    if (tid < 24 && tid < R)
        iymap[tid] = (((ys_blk + tid)*hin)/h - fy0)*8;
    if (tid >= 32 && tid < 56 && (tid-32) < C)
        ixmap[tid-32] = ((xs_blk + tid - 32)*win)/w - fx0;
    __syncthreads();

    // flush stats (one double-atomic per channel per block)
    if (tid < 64){
        atomicAdd(&g_red[0][0][ocbase + tid], (double)ssum[tid]);
        atomicAdd(&g_red[0][1][ocbase + tid], (double)ssq[tid]);
    }

    // coalesced store: each warp owns 8 oc planes, lanes span contiguous x
    int wid = tid >> 5, lane = tid & 31;
    for (int oc8 = 0; oc8 < 8; oc8++){
        int oc = wid*8 + oc8;
        const float* sv = &sval[oc*65];
        float* op = g_out224 + ((size_t)(b*NC + ocbase + oc)*IMG + t)*IMG + l;
        for (int yy = 0; yy < R; yy++){
            int iyl = iymap[yy];
            float* orow = op + (ys_blk + yy)*IMG + xs_blk;
            for (int xx = lane; xx < C; xx += 32)
                orow[xx] = sv[iyl + ixmap[xx]];
        }
    }
}

// ---------------- BN reductions ----------------
__global__ void zero_red(){
    if (threadIdx.x < 512) ((double*)g_red)[threadIdx.x] = 0.0;
}

__global__ void bn_finalize(const float* __restrict__ g, const float* __restrict__ bta,
                            int layer, double invN){
    int c = threadIdx.x;
    if (c >= NC) return;
    double m   = g_red[layer][0][c]*invN;
    double var = g_red[layer][1][c]*invN - m*m;
    float rs = (float)(1.0/sqrt(var + 1e-5));
    float sc = g[c]*rs;
    g_ss[layer][c] = make_float2(sc, bta[c] - (float)m*sc);
}

// ---------------- bn1 + relu + maxpool 3x3 s2 p1 (4 outputs/thread, float4 I/O) --
__global__ void pool_bn1(){
    int idx = blockIdx.x*256 + threadIdx.x;
    if (idx >= B*NC*112*28) return;
    int xq = idx % 28;
    int t1 = idx / 28;
    int oy = t1 % 112;
    int t2 = t1 / 112;
    int c  = t2 % NC;
    int bb = t2 / NC;
    float2 ss = g_ss[0][c];
    const float* p = g_out224 + (size_t)(bb*NC + c)*HW1;
    int gx0 = xq*8;                 // input x base; need gx0-1 .. gx0+7

    float m0 = 0.f, m1 = 0.f, m2 = 0.f, m3 = 0.f;
    #pragma unroll
    for (int i = 0; i < 3; i++){
        int y = 2*oy - 1 + i;
        if ((unsigned)y >= (unsigned)IMG) continue;
        const float* row = p + y*IMG;
        float f[9];
        if (xq > 0){
            float4 A = *(const float4*)(row + gx0 - 4);
            f[0] = A.w;
        } else f[0] = 0.f;
        float4 Bv = *(const float4*)(row + gx0);
        float4 Cv = *(const float4*)(row + gx0 + 4);
        f[1]=Bv.x; f[2]=Bv.y; f[3]=Bv.z; f[4]=Bv.w;
        f[5]=Cv.x; f[6]=Cv.y; f[7]=Cv.z; f[8]=Cv.w;
        float v[9];
        #pragma unroll
        for (int k = 0; k < 9; k++) v[k] = fmaxf(fmaf(f[k], ss.x, ss.y), 0.f);
        if (xq == 0) v[0] = 0.f;
        m0 = fmaxf(m0, fmaxf(v[0], fmaxf(v[1], v[2])));
        m1 = fmaxf(m1, fmaxf(v[2], fmaxf(v[3], v[4])));
        m2 = fmaxf(m2, fmaxf(v[4], fmaxf(v[5], v[6])));
        m3 = fmaxf(m3, fmaxf(v[6], fmaxf(v[7], v[8])));
    }
    *(float4*)&g_x112[((size_t)(bb*NC + c)*112 + oy)*112 + xq*4] =
        make_float4(m0, m1, m2, m3);
}

// ---------------- conv2 3x3 pad1 (128->128) + float4 stores + fused stats -------
__global__ __launch_bounds__(256,2) void conv2_all(const float* __restrict__ w2){
    __shared__ __align__(16) float ws[72*64];      // [icl*9+tap][oc]
    __shared__ __align__(16) ull   ins[8*18*20];   // [icl][18][20] dup'd
    __shared__ float ssum[64], ssq[64];
    int oy0 = blockIdx.y*16, ox0 = blockIdx.x*16;
    int b = blockIdx.z >> 1, ocbase = (blockIdx.z & 1)*64;
    int tid = threadIdx.x;
    int ocg = tid & 15, pxg = tid >> 4;
    int r0 = (pxg >> 2)*4, c0 = (pxg & 3)*4;

    if (tid < 64){ ssum[tid] = 0.f; ssq[tid] = 0.f; }

    ull acc[2][16];
    #pragma unroll
    for (int i = 0; i < 16; i++){ acc[0][i] = 0; acc[1][i] = 0; }

    for (int icc = 0; icc < 16; icc++){
        __syncthreads();
        {
            int o = tid >> 2, k0 = (tid & 3)*18;
            const float* wr = w2 + ((size_t)(ocbase + o)*NC + icc*8)*9;
            #pragma unroll
            for (int j = 0; j < 18; j++)
                ws[(k0 + j)*64 + o] = wr[k0 + j];
        }
        for (int i = tid; i < 8*18*18; i += 256){
            int icl = i/324, rem = i - icl*324, y = rem/18, x = rem - y*18;
            int gy = oy0 - 1 + y, gx = ox0 - 1 + x;
            float v = 0.f;
            if ((unsigned)gy < 112u && (unsigned)gx < 112u)
                v = g_x112[((size_t)(b*NC + icc*8 + icl)*112 + gy)*112 + gx];
            ins[(icl*18 + y)*20 + x] = pack2(v);
        }
        __syncthreads();

        for (int icl = 0; icl < 8; icl++){
            #pragma unroll
            for (int ky = 0; ky < 3; ky++){
                const ull* iprow = &ins[(icl*18 + r0 + ky)*20 + c0];
                #pragma unroll
                for (int kx = 0; kx < 3; kx++){
                    ulonglong2 wv = *(const ulonglong2*)&ws[((icl*9 + ky*3 + kx)<<6) + ocg*4];
                    if (kx != 1){
                        #pragma unroll
                        for (int pyy = 0; pyy < 4; pyy++){
                            ulonglong2 a01 = *(const ulonglong2*)(iprow + pyy*20 + kx);
                            ulonglong2 a23 = *(const ulonglong2*)(iprow + pyy*20 + kx + 2);
                            acc[0][pyy*4+0] = ffma2(wv.x, a01.x, acc[0][pyy*4+0]);
                            acc[1][pyy*4+0] = ffma2(wv.y, a01.x, acc[1][pyy*4+0]);
                            acc[0][pyy*4+1] = ffma2(wv.x, a01.y, acc[0][pyy*4+1]);
                            acc[1][pyy*4+1] = ffma2(wv.y, a01.y, acc[1][pyy*4+1]);
                            acc[0][pyy*4+2] = ffma2(wv.x, a23.x, acc[0][pyy*4+2]);
                            acc[1][pyy*4+2] = ffma2(wv.y, a23.x, acc[1][pyy*4+2]);
                            acc[0][pyy*4+3] = ffma2(wv.x, a23.y, acc[0][pyy*4+3]);
                            acc[1][pyy*4+3] = ffma2(wv.y, a23.y, acc[1][pyy*4+3]);
                        }
                    } else {
                        #pragma unroll
                        for (int pyy = 0; pyy < 4; pyy++){
                            #pragma unroll
                            for (int pxx = 0; pxx < 4; pxx++){
                                ull iv2 = iprow[pyy*20 + kx + pxx];
                                acc[0][pyy*4+pxx] = ffma2(wv.x, iv2, acc[0][pyy*4+pxx]);
                                acc[1][pyy*4+pxx] = ffma2(wv.y, iv2, acc[1][pyy*4+pxx]);
                            }
                        }
                    }
                }
            }
        }
    }

    // epilogue: float4 stores (coalesced 32B lane-pairs) + fused BN2 stats
    float ps[4] = {0,0,0,0}, pq[4] = {0,0,0,0};
    #pragma unroll
    for (int pyy = 0; pyy < 4; pyy++){
        float vals[4][4];
        #pragma unroll
        for (int pxx = 0; pxx < 4; pxx++){
            float2 v0 = unpack2(acc[0][pyy*4+pxx]);
            float2 v1 = unpack2(acc[1][pyy*4+pxx]);
            vals[0][pxx] = v0.x; vals[1][pxx] = v0.y;
            vals[2][pxx] = v1.x; vals[3][pxx] = v1.y;
        }
        size_t rowoff = (size_t)(oy0 + r0 + pyy)*112 + ox0 + c0;
        #pragma unroll
        for (int oi = 0; oi < 4; oi++){
            #pragma unroll
            for (int pxx = 0; pxx < 4; pxx++){
                float v = vals[oi][pxx];
                ps[oi] += v; pq[oi] += v*v;
            }
            *(float4*)&g_y112[(size_t)(b*NC + ocbase + ocg*4 + oi)*HW2 + rowoff] =
                make_float4(vals[oi][0], vals[oi][1], vals[oi][2], vals[oi][3]);
        }
    }
    #pragma unroll
    for (int oi = 0; oi < 4; oi++){
        atomicAdd(&ssum[ocg*4+oi], ps[oi]);
        atomicAdd(&ssq [ocg*4+oi], pq[oi]);
    }
    __syncthreads();
    if (tid < 64){
        atomicAdd(&g_red[1][0][ocbase + tid], (double)ssum[tid]);
        atomicAdd(&g_red[1][1][ocbase + tid], (double)ssq[tid]);
    }
}

// ---------------- final bn2 + relu (float4, 4 elems/thread) ----------------
__global__ void finalize_out(float* __restrict__ out){
    int q = blockIdx.x*256 + threadIdx.x;
    if (q >= B*NC*HW2/4) return;
    int c = (q / (HW2/4)) % NC;        // 4-group never straddles a channel
    float2 ss = g_ss[1][c];
    float4 v = *(const float4*)&g_y112[(size_t)q*4];
    v.x = fmaxf(fmaf(v.x, ss.x, ss.y), 0.f);
    v.y = fmaxf(fmaf(v.y, ss.x, ss.y), 0.f);
    v.z = fmaxf(fmaf(v.z, ss.x, ss.y), 0.f);
    v.w = fmaxf(fmaf(v.w, ss.x, ss.y), 0.f);
    *(float4*)&out[(size_t)q*4] = v;
}

// ---------------- host: window geometry (replicates numpy/float32 exactly) ------
static void build_wins(int* Wt, int* dstot, int* b1tot){
    float scales[7];
    for (int i = 0; i < 7; i++){
        double v = 2.0 + (double)i*((1.0 - 2.0)/6.0);
        if (i == 6) v = 1.0;
        scales[i] = (float)v;
    }
    int xoff = 0, ds = 0, b1 = 0, wi = 0;
    for (int s = 0; s < 7; s++){
        int a = 16*s, bb = 16*(s+1), c = 224 - bb, d = 224 - a;
        int rect[4][4] = {{a,a,bb,c},{bb,a,d,bb},{c,bb,d,d},{a,c,c,d}};
        for (int r = 0; r < 4; r++){
            int t = rect[r][0], l = rect[r][1], bo = rect[r][2], rr = rect[r][3];
            int h = bo - t, w = rr - l;
            volatile float fh = (float)(h + 12), fw = (float)(w + 12);
            int sh = (int)(fh / scales[s]);
            int sw = (int)(fw / scales[s]);
            int* e = Wt + wi*9;
            e[0]=t; e[1]=l; e[2]=h; e[3]=w; e[4]=sh; e[5]=sw;
            e[6]=xoff; e[7]=ds; e[8]=b1;
            xoff += sh*sw;
            ds   += sh * ((sw + 63)/64);
            int hin = sh - 6, win = sw - 6;
            b1   += ((hin + 7)/8) * ((win + 7)/8);
            wi++;
        }
    }
    *dstot = ds; *b1tot = b1;
}

extern "C" void kernel_launch(void* const* d_in, const int* in_sizes, int n_in,
                              void* d_out, int out_size){
    const float* inp    = (const float*)d_in[0];
    const float* w1     = (const float*)d_in[1];
    const float* gamma1 = (const float*)d_in[2];
    const float* beta1  = (const float*)d_in[3];
    const float* w2     = (const float*)d_in[4];
    const float* gamma2 = (const float*)d_in[5];
    const float* beta2  = (const float*)d_in[6];
    float* out = (float*)d_out;

    WinTab wt;
    int dstot = 0, b1tot = 0;
    build_wins(wt.f, &dstot, &b1tot);

    zero_red<<<1,512>>>();
    ds_all<<<dim3(dstot,1,B*3), 64>>>(inp, wt);
    conv1_all<<<dim3(b1tot,1,B*2), 256>>>(w1, wt);
    bn_finalize<<<1,128>>>(gamma1, beta1, 0, 1.0/((double)B*HW1));
    pool_bn1<<<(B*NC*112*28 + 255)/256, 256>>>();
    conv2_all<<<dim3(7,7,B*2), 256>>>(w2);
    bn_finalize<<<1,128>>>(gamma2, beta2, 1, 1.0/((double)B*HW2));
    finalize_out<<<(B*NC*HW2/4 + 255)/256, 256>>>(out);
}